// round 5
// baseline (speedup 1.0000x reference)
#include <cuda_runtime.h>
#include <cuda_bf16.h>
#include <math.h>
#include <stdint.h>

// Problem constants
#define Bc  4
#define Tc  4096
#define Dc  1024
#define Hc  16
#define HDc 64
#define Kc  32

// ---------------- scratch (static device arrays) ----------------
__device__ float g_qkv[(size_t)Bc * Tc * 3 * Dc];           // (B,T,3,H,HD) fp32
__device__ float g_spec[(size_t)3 * Bc * Hc * Kc * HDc];    // q/k/v spectral
__device__ float g_ws[(size_t)Bc * Hc * Kc * HDc];          // response * v_spec
__device__ __nv_bfloat16 g_xhi[(size_t)Bc * Tc * Dc];
__device__ __nv_bfloat16 g_xlo[(size_t)Bc * Tc * Dc];
__device__ __nv_bfloat16 g_wqhi[(size_t)3 * Dc * Dc];
__device__ __nv_bfloat16 g_wqlo[(size_t)3 * Dc * Dc];
__device__ __nv_bfloat16 g_wohi[(size_t)Dc * Dc];
__device__ __nv_bfloat16 g_wolo[(size_t)Dc * Dc];
__device__ __nv_bfloat16 g_mhi[(size_t)Bc * Tc * Dc];
__device__ __nv_bfloat16 g_mlo[(size_t)Bc * Tc * Dc];

__device__ __forceinline__ uint32_t smem_u32(const void* p) {
    uint32_t a;
    asm("{ .reg .u64 t; cvta.to.shared.u64 t, %1; cvt.u32.u64 %0, t; }"
        : "=r"(a) : "l"(p));
    return a;
}

// ---------------------------------------------------------------------------
// Tensor-core GEMM (NT) via mma.sync (HMMA): C[M,N] = A*B^T.
// A,B given as bf16 hi/lo split pairs, row-major [rows, 1024].
// C = Ahi*Bhi^T + Ahi*Blo^T + Alo*Bhi^T   (fp32 accum)
// 128x128 CTA tile, K-tile 32, cp.async double buffer, 8 warps (2x4),
// each warp 64x32 via m16n8k16.
// SMEM tiles: 128 rows x 32 bf16, rows padded to 80B (conflict-free ldmatrix).
// ---------------------------------------------------------------------------
#define KT      32
#define RB      80                 // padded row bytes (32 bf16 = 64B data)
#define TILE_B  (128 * RB)         // 10240 B per tile
#define STAGE_B (4 * TILE_B)       // Ahi,Alo,Bhi,Blo per stage

__global__ void __launch_bounds__(256) gemm_mma(
    const __nv_bfloat16* __restrict__ Ahi, const __nv_bfloat16* __restrict__ Alo,
    const __nv_bfloat16* __restrict__ Bhi, const __nv_bfloat16* __restrict__ Blo,
    float* __restrict__ C, int M, int N)
{
    extern __shared__ char smem[];
    const int Kd = 1024;
    const uint32_t sbase = smem_u32(smem);
    const int tid = threadIdx.x, wid = tid >> 5, lane = tid & 31;
    const int row0 = blockIdx.y * 128, col0 = blockIdx.x * 128;
    const int wm = wid >> 2, wn = wid & 3;           // warp tile: 64m x 32n

    const __nv_bfloat16* s0 = Ahi + (size_t)row0 * Kd;
    const __nv_bfloat16* s1 = Alo + (size_t)row0 * Kd;
    const __nv_bfloat16* s2 = Bhi + (size_t)col0 * Kd;
    const __nv_bfloat16* s3 = Blo + (size_t)col0 * Kd;

    // per-thread cp.async mapping: 2 chunks per tile (512 chunks / 256 thr)
    const int e0 = tid, e1 = tid + 256;
    const int r0c = e0 >> 2, c0c = e0 & 3;           // row 0..63,  chunk
    const int r1c = e1 >> 2, c1c = e1 & 3;           // row 64..127, chunk

#define LOAD_STAGE(kt, buf)                                                   \
    do {                                                                      \
        uint32_t db = sbase + (buf) * STAGE_B;                                \
        const __nv_bfloat16* srcs[4] = { s0, s1, s2, s3 };                    \
        _Pragma("unroll")                                                     \
        for (int a = 0; a < 4; a++) {                                         \
            const char* g0 = (const char*)(srcs[a] + (size_t)r0c * Kd + (kt) * KT) + c0c * 16; \
            const char* g1 = (const char*)(srcs[a] + (size_t)r1c * Kd + (kt) * KT) + c1c * 16; \
            uint32_t p0 = db + a * TILE_B + r0c * RB + c0c * 16;              \
            uint32_t p1 = db + a * TILE_B + r1c * RB + c1c * 16;              \
            asm volatile("cp.async.cg.shared.global [%0],[%1],16;" :: "r"(p0), "l"(g0)); \
            asm volatile("cp.async.cg.shared.global [%0],[%1],16;" :: "r"(p1), "l"(g1)); \
        }                                                                     \
        asm volatile("cp.async.commit_group;");                               \
    } while (0)

    float acc[4][4][4];
#pragma unroll
    for (int i = 0; i < 4; i++)
#pragma unroll
        for (int j = 0; j < 4; j++)
#pragma unroll
            for (int q = 0; q < 4; q++) acc[i][j][q] = 0.f;

    LOAD_STAGE(0, 0);
    int buf = 0;

    for (int kt = 0; kt < Kd / KT; kt++) {
        if (kt + 1 < Kd / KT) {
            LOAD_STAGE(kt + 1, buf ^ 1);
            asm volatile("cp.async.wait_group 1;");
        } else {
            asm volatile("cp.async.wait_group 0;");
        }
        __syncthreads();

        const uint32_t db = sbase + buf * STAGE_B;
#pragma unroll
        for (int ks = 0; ks < 2; ks++) {
            // A fragments (hi & lo), 4 m-frags each, ldmatrix x4
            uint32_t rah[4][4], ral[4][4];
#pragma unroll
            for (int mf = 0; mf < 4; mf++) {
                int r = wm * 64 + mf * 16 + (lane & 15);
                uint32_t ad = db + r * RB + ks * 32 + ((lane >> 4) & 1) * 16;
                asm volatile("ldmatrix.sync.aligned.m8n8.x4.shared.b16 {%0,%1,%2,%3},[%4];"
                    : "=r"(rah[mf][0]), "=r"(rah[mf][1]), "=r"(rah[mf][2]), "=r"(rah[mf][3])
                    : "r"(ad));
                asm volatile("ldmatrix.sync.aligned.m8n8.x4.shared.b16 {%0,%1,%2,%3},[%4];"
                    : "=r"(ral[mf][0]), "=r"(ral[mf][1]), "=r"(ral[mf][2]), "=r"(ral[mf][3])
                    : "r"(ad + TILE_B));
            }
            // B fragments (hi & lo), 4 n-frags each, ldmatrix x2
            uint32_t rbh[4][2], rbl[4][2];
#pragma unroll
            for (int nf = 0; nf < 4; nf++) {
                int r = wn * 32 + nf * 8 + (lane & 7);
                uint32_t bd = db + 2 * TILE_B + r * RB + ks * 32 + ((lane >> 3) & 1) * 16;
                asm volatile("ldmatrix.sync.aligned.m8n8.x2.shared.b16 {%0,%1},[%2];"
                    : "=r"(rbh[nf][0]), "=r"(rbh[nf][1]) : "r"(bd));
                asm volatile("ldmatrix.sync.aligned.m8n8.x2.shared.b16 {%0,%1},[%2];"
                    : "=r"(rbl[nf][0]), "=r"(rbl[nf][1]) : "r"(bd + TILE_B));
            }
#define MMA(d, A, Bf)                                                         \
    asm volatile("mma.sync.aligned.m16n8k16.row.col.f32.bf16.bf16.f32 "       \
                 "{%0,%1,%2,%3},{%4,%5,%6,%7},{%8,%9},{%0,%1,%2,%3};"         \
                 : "+f"(d[0]), "+f"(d[1]), "+f"(d[2]), "+f"(d[3])             \
                 : "r"(A[0]), "r"(A[1]), "r"(A[2]), "r"(A[3]),                \
                   "r"(Bf[0]), "r"(Bf[1]))
#pragma unroll
            for (int mf = 0; mf < 4; mf++)
#pragma unroll
                for (int nf = 0; nf < 4; nf++) {
                    MMA(acc[mf][nf], rah[mf], rbh[nf]);
                    MMA(acc[mf][nf], rah[mf], rbl[nf]);
                    MMA(acc[mf][nf], ral[mf], rbh[nf]);
                }
#undef MMA
        }
        __syncthreads();
        buf ^= 1;
    }

    // epilogue: fp32 stores, 2 floats per frag-row per thread
    const int mrow = lane >> 2, ncol = (lane & 3) * 2;
#pragma unroll
    for (int mf = 0; mf < 4; mf++) {
#pragma unroll
        for (int nf = 0; nf < 4; nf++) {
            int r  = row0 + wm * 64 + mf * 16 + mrow;
            int cc = col0 + wn * 32 + nf * 8 + ncol;
            *(float2*)(C + (size_t)r * N + cc) =
                make_float2(acc[mf][nf][0], acc[mf][nf][1]);
            *(float2*)(C + (size_t)(r + 8) * N + cc) =
                make_float2(acc[mf][nf][2], acc[mf][nf][3]);
        }
    }
#undef LOAD_STAGE
}

// ---------------------------------------------------------------------------
// fp32 -> bf16 hi/lo split, 4 elems/thread
// ---------------------------------------------------------------------------
__global__ void split_bf16(const float* __restrict__ s,
                           __nv_bfloat16* __restrict__ hi,
                           __nv_bfloat16* __restrict__ lo, int n4)
{
    int i = blockIdx.x * blockDim.x + threadIdx.x;
    if (i >= n4) return;
    float4 v = ((const float4*)s)[i];
    float vv[4] = { v.x, v.y, v.z, v.w };
    __nv_bfloat16 h[4], l[4];
#pragma unroll
    for (int j = 0; j < 4; j++) {
        h[j] = __float2bfloat16_rn(vv[j]);
        l[j] = __float2bfloat16_rn(vv[j] - __bfloat162float(h[j]));
    }
    ((__nv_bfloat162*)hi)[i * 2 + 0] = __halves2bfloat162(h[0], h[1]);
    ((__nv_bfloat162*)hi)[i * 2 + 1] = __halves2bfloat162(h[2], h[3]);
    ((__nv_bfloat162*)lo)[i * 2 + 0] = __halves2bfloat162(l[0], l[1]);
    ((__nv_bfloat162*)lo)[i * 2 + 1] = __halves2bfloat162(l[2], l[3]);
}

// ---------------------------------------------------------------------------
// qm = mean_t q[b,h,t,:] then tiny MLP -> pulse_widths[b,h]
// ---------------------------------------------------------------------------
__global__ __launch_bounds__(256) void qm_pulse_kernel(
    const float* __restrict__ W1, const float* __restrict__ b1,
    const float* __restrict__ W2, const float* __restrict__ b2,
    float* __restrict__ out_pulse)
{
    const int bh = blockIdx.x;
    const int b = bh >> 4, h = bh & 15;
    const int tid = threadIdx.x;
    const int d = tid & 63, chunk = tid >> 6;

    const float* base = g_qkv + (size_t)b * Tc * 3072 + h * 64 + d;
    float s = 0.f;
    const int t0 = chunk * 1024;
    for (int t = t0; t < t0 + 1024; t++)
        s += base[(size_t)t * 3072];

    __shared__ float part[256];
    __shared__ float qm[64];
    part[tid] = s;
    __syncthreads();
    if (tid < 64)
        qm[tid] = (part[tid] + part[tid + 64] + part[tid + 128] + part[tid + 192])
                  * (1.0f / Tc);
    __syncthreads();
    if (tid < 32) {
        float acc = b1[tid];
        for (int dd = 0; dd < 64; dd++)
            acc = fmaf(qm[dd], W1[tid * 64 + dd], acc);
        float h1 = acc / (1.f + expf(-acc));
        float p = h1 * W2[tid];
#pragma unroll
        for (int off = 16; off; off >>= 1)
            p += __shfl_down_sync(0xffffffffu, p, off);
        if (tid == 0) {
            float x = p + b2[0];
            float sp = (x > 20.f) ? x : log1pf(expf(x));
            out_pulse[bh] = 4.0f + sp;
        }
    }
}

// ---------------------------------------------------------------------------
// Spectral projection: spec_s[b,h,k,d] = sum_t qkv_s[b,h,t,d] * sb[b,t,k]
// ---------------------------------------------------------------------------
__global__ __launch_bounds__(256) void spec_kernel(const float* __restrict__ sb)
{
    const int bh = blockIdx.x, s = blockIdx.y;
    const int b = bh >> 4, h = bh & 15;
    const int tid = threadIdx.x;
    const int k = tid >> 3;
    const int d0 = (tid & 7) * 8;

    __shared__ float sbs[64][33];
    __shared__ float qs[64][65];
    float acc[8];
#pragma unroll
    for (int i = 0; i < 8; i++) acc[i] = 0.f;

    const float* qbase = g_qkv + (size_t)b * Tc * 3072 + s * 1024 + h * 64;
    const float* sbase = sb + (size_t)b * Tc * 32;

    for (int t0 = 0; t0 < Tc; t0 += 64) {
#pragma unroll
        for (int i = 0; i < 2; i++) {
            int e = tid + i * 256;
            int tt = e >> 3, k4 = (e & 7) * 4;
            float4 v = *(const float4*)(sbase + (size_t)(t0 + tt) * 32 + k4);
            sbs[tt][k4 + 0] = v.x; sbs[tt][k4 + 1] = v.y;
            sbs[tt][k4 + 2] = v.z; sbs[tt][k4 + 3] = v.w;
        }
#pragma unroll
        for (int i = 0; i < 4; i++) {
            int e = tid + i * 256;
            int tt = e >> 4, d4 = (e & 15) * 4;
            float4 v = *(const float4*)(qbase + (size_t)(t0 + tt) * 3072 + d4);
            qs[tt][d4 + 0] = v.x; qs[tt][d4 + 1] = v.y;
            qs[tt][d4 + 2] = v.z; qs[tt][d4 + 3] = v.w;
        }
        __syncthreads();
        for (int t = 0; t < 64; t++) {
            float sv = sbs[t][k];
#pragma unroll
            for (int i = 0; i < 8; i++)
                acc[i] = fmaf(sv, qs[t][d0 + i], acc[i]);
        }
        __syncthreads();
    }
    float* outp = g_spec + ((size_t)(s * (Bc * Hc) + bh) * Kc + k) * HDc + d0;
#pragma unroll
    for (int i = 0; i < 8; i++) outp[i] = acc[i];
}

// ---------------------------------------------------------------------------
// attn_spec + FitzHugh-Nagumo dynamics (constant along HD -> scalar ODE)
// ---------------------------------------------------------------------------
__global__ void soliton_kernel(
    const float* __restrict__ d_a, const float* __restrict__ d_b,
    const float* __restrict__ filt, float* __restrict__ out_resp)
{
    const int idx = blockIdx.x * blockDim.x + threadIdx.x;
    if (idx >= Bc * Hc * Kc) return;
    const int bh = idx >> 5, k = idx & 31;
    const int h = bh & 15;

    const size_t specN = (size_t)Bc * Hc * Kc * HDc;
    const float* qv = g_spec + (size_t)idx * 64;
    const float* kv = g_spec + specN + (size_t)idx * 64;
    float dot = 0.f;
#pragma unroll
    for (int d = 0; d < 64; d++) dot = fmaf(qv[d], kv[d], dot);

    float f = 1.f / (1.f + expf(-filt[h * 32 + k]));
    float stim = dot * 0.125f * f;

    const float a = d_a[0], bb = d_b[0];
    float scale = fmaxf(fabsf(stim), 1e-6f);
    float sn = stim / scale;
    float I = (fabsf(stim) > 0.5f) ? sn : sn * 0.1f;
    float v = 0.f, w = 0.f;
    const float dt = 0.2f;
#pragma unroll
    for (int s = 0; s < 5; s++) {
        float dv = v - v * v * v * (1.f / 3.f) - w + I;
        float dw = (v + a - bb * w) * 10.f;
        v = fminf(fmaxf(v + dt * dv, -3.f), 3.f);
        w = fminf(fmaxf(w + dt * dw, -3.f), 3.f);
    }
    float resp = v * scale;
    out_resp[idx] = resp;

    const float* vv = g_spec + 2 * specN + (size_t)idx * 64;
    float* ws = g_ws + (size_t)idx * 64;
#pragma unroll
    for (int d = 0; d < 64; d++) ws[d] = resp * vv[d];
}

// ---------------------------------------------------------------------------
// Recombine: mid[b,t,h*64+d] = sum_k sb[b,t,k] * ws[b,h,k,d] -> bf16 hi/lo
// ---------------------------------------------------------------------------
__global__ __launch_bounds__(256) void recombine_kernel(const float* __restrict__ sb)
{
    const int bh = blockIdx.x;
    const int b = bh >> 4, h = bh & 15;
    const int t0 = blockIdx.y * 128;
    const int tid = threadIdx.x;

    __shared__ float ws_s[32][65];
    __shared__ float sbs[128][33];

#pragma unroll
    for (int i = 0; i < 2; i++) {
        int e = tid + i * 256;
        int kk = e >> 4, d4 = (e & 15) * 4;
        float4 v = *(const float4*)(g_ws + ((size_t)bh * 32 + kk) * 64 + d4);
        ws_s[kk][d4 + 0] = v.x; ws_s[kk][d4 + 1] = v.y;
        ws_s[kk][d4 + 2] = v.z; ws_s[kk][d4 + 3] = v.w;
    }
    const float* sbase = sb + (size_t)b * Tc * 32;
#pragma unroll
    for (int i = 0; i < 4; i++) {
        int e = tid + i * 256;
        int tt = e >> 3, k4 = (e & 7) * 4;
        float4 v = *(const float4*)(sbase + (size_t)(t0 + tt) * 32 + k4);
        sbs[tt][k4 + 0] = v.x; sbs[tt][k4 + 1] = v.y;
        sbs[tt][k4 + 2] = v.z; sbs[tt][k4 + 3] = v.w;
    }
    __syncthreads();

    for (int e = tid; e < 128 * 64; e += 256) {
        int t = e >> 6, d = e & 63;
        float acc = 0.f;
#pragma unroll
        for (int k = 0; k < 32; k++)
            acc = fmaf(sbs[t][k], ws_s[k][d], acc);
        size_t oi = (size_t)(b * Tc + t0 + t) * Dc + h * 64 + d;
        __nv_bfloat16 hh = __float2bfloat16_rn(acc);
        g_mhi[oi] = hh;
        g_mlo[oi] = __float2bfloat16_rn(acc - __bfloat162float(hh));
    }
}

// ---------------------------------------------------------------------------
// Launch
// ---------------------------------------------------------------------------
extern "C" void kernel_launch(void* const* d_in, const int* in_sizes, int n_in,
                              void* d_out, int out_size)
{
    const float* x    = (const float*)d_in[0];
    const float* sb   = (const float*)d_in[1];
    const float* Wqkv = (const float*)d_in[2];
    const float* Wout = (const float*)d_in[3];
    const float* a    = (const float*)d_in[4];
    const float* b    = (const float*)d_in[5];
    const float* W1   = (const float*)d_in[6];
    const float* b1   = (const float*)d_in[7];
    const float* W2   = (const float*)d_in[8];
    const float* b2   = (const float*)d_in[9];
    const float* filt = (const float*)d_in[10];

    float* out       = (float*)d_out;
    float* out_pulse = out + (size_t)Bc * Tc * Dc;
    float* out_resp  = out_pulse + Bc * Hc;

    float* pqkv = nullptr;
    cudaGetSymbolAddress((void**)&pqkv, g_qkv);
    __nv_bfloat16 *pxhi, *pxlo, *pwqhi, *pwqlo, *pwohi, *pwolo, *pmhi, *pmlo;
    cudaGetSymbolAddress((void**)&pxhi, g_xhi);
    cudaGetSymbolAddress((void**)&pxlo, g_xlo);
    cudaGetSymbolAddress((void**)&pwqhi, g_wqhi);
    cudaGetSymbolAddress((void**)&pwqlo, g_wqlo);
    cudaGetSymbolAddress((void**)&pwohi, g_wohi);
    cudaGetSymbolAddress((void**)&pwolo, g_wolo);
    cudaGetSymbolAddress((void**)&pmhi, g_mhi);
    cudaGetSymbolAddress((void**)&pmlo, g_mlo);

    const int GEMM_SMEM = 2 * STAGE_B;   // 81920 B
    cudaFuncSetAttribute(gemm_mma, cudaFuncAttributeMaxDynamicSharedMemorySize, GEMM_SMEM);

    // 0) bf16 hi/lo splits
    {
        int n4 = (Bc * Tc * Dc) / 4;
        split_bf16<<<(n4 + 255) / 256, 256>>>(x, pxhi, pxlo, n4);
        n4 = (3 * Dc * Dc) / 4;
        split_bf16<<<(n4 + 255) / 256, 256>>>(Wqkv, pwqhi, pwqlo, n4);
        n4 = (Dc * Dc) / 4;
        split_bf16<<<(n4 + 255) / 256, 256>>>(Wout, pwohi, pwolo, n4);
    }

    // 1) QKV projection: (16384 x 1024) @ (3072 x 1024)^T  [mma.sync bf16]
    gemm_mma<<<dim3(3 * Dc / 128, Bc * Tc / 128), 256, GEMM_SMEM>>>(
        pxhi, pxlo, pwqhi, pwqlo, pqkv, Bc * Tc, 3 * Dc);

    // 2) Pulse widths
    qm_pulse_kernel<<<Bc * Hc, 256>>>(W1, b1, W2, b2, out_pulse);

    // 3) Spectral projections q/k/v
    spec_kernel<<<dim3(Bc * Hc, 3), 256>>>(sb);

    // 4) soliton dynamics + ws
    soliton_kernel<<<(Bc * Hc * Kc + 255) / 256, 256>>>(a, b, filt, out_resp);

    // 5) Recombine -> mid (bf16 hi/lo)
    recombine_kernel<<<dim3(Bc * Hc, Tc / 128), 256>>>(sb);

    // 6) Output projection: (16384 x 1024) @ (1024 x 1024)^T  [mma.sync bf16]
    gemm_mma<<<dim3(Dc / 128, Bc * Tc / 128), 256, GEMM_SMEM>>>(
        pmhi, pmlo, pwohi, pwolo, out, Bc * Tc, Dc);
}

// round 6
// speedup vs baseline: 1.4102x; 1.4102x over previous
#include <cuda_runtime.h>
#include <cuda_bf16.h>
#include <math.h>
#include <stdint.h>

// Problem constants
#define Bc  4
#define Tc  4096
#define Dc  1024
#define Hc  16
#define HDc 64
#define Kc  32
#define NSLICE 4

// ---------------- scratch (static device arrays) ----------------
__device__ float g_qkv[(size_t)Bc * Tc * 3 * Dc];           // (B,T,3,H,HD) fp32
__device__ float g_spec[(size_t)3 * Bc * Hc * Kc * HDc];    // q/k/v spectral
__device__ float g_specp[NSLICE][(size_t)3 * Bc * Hc * Kc * HDc];
__device__ float g_ws[(size_t)Bc * Hc * Kc * HDc];          // response * v_spec
__device__ __nv_bfloat16 g_xhi[(size_t)Bc * Tc * Dc];
__device__ __nv_bfloat16 g_xlo[(size_t)Bc * Tc * Dc];
__device__ __nv_bfloat16 g_wqhi[(size_t)3 * Dc * Dc];
__device__ __nv_bfloat16 g_wqlo[(size_t)3 * Dc * Dc];
__device__ __nv_bfloat16 g_wohi[(size_t)Dc * Dc];
__device__ __nv_bfloat16 g_wolo[(size_t)Dc * Dc];
__device__ __nv_bfloat16 g_mhi[(size_t)Bc * Tc * Dc];
__device__ __nv_bfloat16 g_mlo[(size_t)Bc * Tc * Dc];

__device__ __forceinline__ uint32_t smem_u32(const void* p) {
    uint32_t a;
    asm("{ .reg .u64 t; cvta.to.shared.u64 t, %1; cvt.u32.u64 %0, t; }"
        : "=r"(a) : "l"(p));
    return a;
}

// ---------------------------------------------------------------------------
// Tensor-core GEMM (NT) via mma.sync (HMMA): C[M,N] = A*B^T.
// C = Ahi*Bhi^T + Ahi*Blo^T + Alo*Bhi^T   (fp32 accum)
// 128x128 CTA tile, K-tile 32, cp.async double buffer (ONE sync per K-tile),
// 8 warps (2x4), warp tile 64x32 via m16n8k16, B frags via ldmatrix.x4.
// SMEM rows padded to 80B -> conflict-free ldmatrix without swizzle.
// ---------------------------------------------------------------------------
#define KT      32
#define RB      80                 // padded row bytes (32 bf16 = 64B data)
#define TILE_B  (128 * RB)         // 10240 B per tile
#define STAGE_B (4 * TILE_B)       // Ahi,Alo,Bhi,Blo per stage

__global__ void __launch_bounds__(256) gemm_mma(
    const __nv_bfloat16* __restrict__ Ahi, const __nv_bfloat16* __restrict__ Alo,
    const __nv_bfloat16* __restrict__ Bhi, const __nv_bfloat16* __restrict__ Blo,
    float* __restrict__ C, int M, int N)
{
    extern __shared__ char smem[];
    const int Kd = 1024;
    const uint32_t sbase = smem_u32(smem);
    const int tid = threadIdx.x, wid = tid >> 5, lane = tid & 31;
    const int row0 = blockIdx.y * 128, col0 = blockIdx.x * 128;
    const int wm = wid >> 2, wn = wid & 3;           // warp tile: 64m x 32n

    const __nv_bfloat16* s0 = Ahi + (size_t)row0 * Kd;
    const __nv_bfloat16* s1 = Alo + (size_t)row0 * Kd;
    const __nv_bfloat16* s2 = Bhi + (size_t)col0 * Kd;
    const __nv_bfloat16* s3 = Blo + (size_t)col0 * Kd;

    const int e0 = tid, e1 = tid + 256;
    const int r0c = e0 >> 2, c0c = e0 & 3;
    const int r1c = e1 >> 2, c1c = e1 & 3;

#define LOAD_STAGE(kt, buf)                                                   \
    do {                                                                      \
        uint32_t db = sbase + (buf) * STAGE_B;                                \
        const __nv_bfloat16* srcs[4] = { s0, s1, s2, s3 };                    \
        _Pragma("unroll")                                                     \
        for (int a = 0; a < 4; a++) {                                         \
            const char* g0 = (const char*)(srcs[a] + (size_t)r0c * Kd + (kt) * KT) + c0c * 16; \
            const char* g1 = (const char*)(srcs[a] + (size_t)r1c * Kd + (kt) * KT) + c1c * 16; \
            uint32_t p0 = db + a * TILE_B + r0c * RB + c0c * 16;              \
            uint32_t p1 = db + a * TILE_B + r1c * RB + c1c * 16;              \
            asm volatile("cp.async.cg.shared.global [%0],[%1],16;" :: "r"(p0), "l"(g0)); \
            asm volatile("cp.async.cg.shared.global [%0],[%1],16;" :: "r"(p1), "l"(g1)); \
        }                                                                     \
        asm volatile("cp.async.commit_group;");                               \
    } while (0)

    float acc[4][4][4];
#pragma unroll
    for (int i = 0; i < 4; i++)
#pragma unroll
        for (int j = 0; j < 4; j++)
#pragma unroll
            for (int q = 0; q < 4; q++) acc[i][j][q] = 0.f;

    LOAD_STAGE(0, 0);
    int buf = 0;

    for (int kt = 0; kt < Kd / KT; kt++) {
        asm volatile("cp.async.wait_group 0;");
        __syncthreads();                 // stage 'buf' visible; buf^1 free
        if (kt + 1 < Kd / KT) LOAD_STAGE(kt + 1, buf ^ 1);

        const uint32_t db = sbase + buf * STAGE_B;
#pragma unroll
        for (int ks = 0; ks < 2; ks++) {
            // A fragments (hi & lo): 4 m-frags each via ldmatrix.x4
            uint32_t rah[4][4], ral[4][4];
#pragma unroll
            for (int mf = 0; mf < 4; mf++) {
                int r = wm * 64 + mf * 16 + (lane & 15);
                uint32_t ad = db + r * RB + ks * 32 + ((lane >> 4) & 1) * 16;
                asm volatile("ldmatrix.sync.aligned.m8n8.x4.shared.b16 {%0,%1,%2,%3},[%4];"
                    : "=r"(rah[mf][0]), "=r"(rah[mf][1]), "=r"(rah[mf][2]), "=r"(rah[mf][3])
                    : "r"(ad));
                asm volatile("ldmatrix.sync.aligned.m8n8.x4.shared.b16 {%0,%1,%2,%3},[%4];"
                    : "=r"(ral[mf][0]), "=r"(ral[mf][1]), "=r"(ral[mf][2]), "=r"(ral[mf][3])
                    : "r"(ad + TILE_B));
            }
            // B fragments (hi & lo): 2 nf-pairs via ldmatrix.x4
            // regs: {nf:k0, nf:k1, nf+1:k0, nf+1:k1}
            uint32_t rbh[2][4], rbl[2][4];
#pragma unroll
            for (int np = 0; np < 2; np++) {
                int r = wn * 32 + (np * 2 + (lane >> 4)) * 8 + (lane & 7);
                uint32_t bd = db + 2 * TILE_B + r * RB + ks * 32 + ((lane >> 3) & 1) * 16;
                asm volatile("ldmatrix.sync.aligned.m8n8.x4.shared.b16 {%0,%1,%2,%3},[%4];"
                    : "=r"(rbh[np][0]), "=r"(rbh[np][1]), "=r"(rbh[np][2]), "=r"(rbh[np][3])
                    : "r"(bd));
                asm volatile("ldmatrix.sync.aligned.m8n8.x4.shared.b16 {%0,%1,%2,%3},[%4];"
                    : "=r"(rbl[np][0]), "=r"(rbl[np][1]), "=r"(rbl[np][2]), "=r"(rbl[np][3])
                    : "r"(bd + TILE_B));
            }
#define MMA(d, A, b0, b1)                                                     \
    asm volatile("mma.sync.aligned.m16n8k16.row.col.f32.bf16.bf16.f32 "       \
                 "{%0,%1,%2,%3},{%4,%5,%6,%7},{%8,%9},{%0,%1,%2,%3};"         \
                 : "+f"(d[0]), "+f"(d[1]), "+f"(d[2]), "+f"(d[3])             \
                 : "r"(A[0]), "r"(A[1]), "r"(A[2]), "r"(A[3]),                \
                   "r"(b0), "r"(b1))
            // product-major ordering: breaks RAW chains on accumulators
#pragma unroll
            for (int mf = 0; mf < 4; mf++)
#pragma unroll
                for (int nf = 0; nf < 4; nf++)
                    MMA(acc[mf][nf], rah[mf], rbh[nf >> 1][(nf & 1) * 2],
                        rbh[nf >> 1][(nf & 1) * 2 + 1]);
#pragma unroll
            for (int mf = 0; mf < 4; mf++)
#pragma unroll
                for (int nf = 0; nf < 4; nf++)
                    MMA(acc[mf][nf], rah[mf], rbl[nf >> 1][(nf & 1) * 2],
                        rbl[nf >> 1][(nf & 1) * 2 + 1]);
#pragma unroll
            for (int mf = 0; mf < 4; mf++)
#pragma unroll
                for (int nf = 0; nf < 4; nf++)
                    MMA(acc[mf][nf], ral[mf], rbh[nf >> 1][(nf & 1) * 2],
                        rbh[nf >> 1][(nf & 1) * 2 + 1]);
#undef MMA
        }
        __syncthreads();                 // all reads of 'buf' done
        buf ^= 1;
    }

    const int mrow = lane >> 2, ncol = (lane & 3) * 2;
#pragma unroll
    for (int mf = 0; mf < 4; mf++) {
#pragma unroll
        for (int nf = 0; nf < 4; nf++) {
            int r  = row0 + wm * 64 + mf * 16 + mrow;
            int cc = col0 + wn * 32 + nf * 8 + ncol;
            *(float2*)(C + (size_t)r * N + cc) =
                make_float2(acc[mf][nf][0], acc[mf][nf][1]);
            *(float2*)(C + (size_t)(r + 8) * N + cc) =
                make_float2(acc[mf][nf][2], acc[mf][nf][3]);
        }
    }
#undef LOAD_STAGE
}

// ---------------------------------------------------------------------------
// fp32 -> bf16 hi/lo split, 4 elems/thread
// ---------------------------------------------------------------------------
__global__ void split_bf16(const float* __restrict__ s,
                           __nv_bfloat16* __restrict__ hi,
                           __nv_bfloat16* __restrict__ lo, int n4)
{
    int i = blockIdx.x * blockDim.x + threadIdx.x;
    if (i >= n4) return;
    float4 v = ((const float4*)s)[i];
    float vv[4] = { v.x, v.y, v.z, v.w };
    __nv_bfloat16 h[4], l[4];
#pragma unroll
    for (int j = 0; j < 4; j++) {
        h[j] = __float2bfloat16_rn(vv[j]);
        l[j] = __float2bfloat16_rn(vv[j] - __bfloat162float(h[j]));
    }
    ((__nv_bfloat162*)hi)[i * 2 + 0] = __halves2bfloat162(h[0], h[1]);
    ((__nv_bfloat162*)hi)[i * 2 + 1] = __halves2bfloat162(h[2], h[3]);
    ((__nv_bfloat162*)lo)[i * 2 + 0] = __halves2bfloat162(l[0], l[1]);
    ((__nv_bfloat162*)lo)[i * 2 + 1] = __halves2bfloat162(l[2], l[3]);
}

// ---------------------------------------------------------------------------
// qm = mean_t q[b,h,t,:] then tiny MLP -> pulse_widths[b,h]
// ---------------------------------------------------------------------------
__global__ __launch_bounds__(256) void qm_pulse_kernel(
    const float* __restrict__ W1, const float* __restrict__ b1,
    const float* __restrict__ W2, const float* __restrict__ b2,
    float* __restrict__ out_pulse)
{
    const int bh = blockIdx.x;
    const int b = bh >> 4, h = bh & 15;
    const int tid = threadIdx.x;
    const int d = tid & 63, chunk = tid >> 6;

    const float* base = g_qkv + (size_t)b * Tc * 3072 + h * 64 + d;
    float s = 0.f;
    const int t0 = chunk * 1024;
    for (int t = t0; t < t0 + 1024; t++)
        s += base[(size_t)t * 3072];

    __shared__ float part[256];
    __shared__ float qm[64];
    part[tid] = s;
    __syncthreads();
    if (tid < 64)
        qm[tid] = (part[tid] + part[tid + 64] + part[tid + 128] + part[tid + 192])
                  * (1.0f / Tc);
    __syncthreads();
    if (tid < 32) {
        float acc = b1[tid];
        for (int dd = 0; dd < 64; dd++)
            acc = fmaf(qm[dd], W1[tid * 64 + dd], acc);
        float h1 = acc / (1.f + expf(-acc));
        float p = h1 * W2[tid];
#pragma unroll
        for (int off = 16; off; off >>= 1)
            p += __shfl_down_sync(0xffffffffu, p, off);
        if (tid == 0) {
            float x = p + b2[0];
            float sp = (x > 20.f) ? x : log1pf(expf(x));
            out_pulse[bh] = 4.0f + sp;
        }
    }
}

// ---------------------------------------------------------------------------
// Spectral projection, register-tiled + T-sliced:
// specp[slice][s,bh,k,d] = sum_{t in slice} qkv_s[b,h,t,d] * sb[b,t,k]
// Block (bh, s, slice); 256 threads: kg(4k) x dg(8d) x sub(4 t-phases).
// 32 FMA per 3 x float4 LDS (broadcast-heavy) -> FMA-bound.
// ---------------------------------------------------------------------------
__global__ __launch_bounds__(256) void spec_part_kernel(const float* __restrict__ sb)
{
    const int bh = blockIdx.x, s = blockIdx.y, slice = blockIdx.z;
    const int b = bh >> 4, h = bh & 15;
    const int tid = threadIdx.x;
    const int k0 = (tid & 7) * 4;
    const int d0 = ((tid >> 3) & 7) * 8;
    const int sub = tid >> 6;

    __shared__ __align__(16) float buf[8192];   // 32KB, dual-purpose
    float* sbs = buf;                           // [64][36]
    float* qs  = buf + 64 * 36;                 // [64][68]

    float acc[4][8];
#pragma unroll
    for (int i = 0; i < 4; i++)
#pragma unroll
        for (int j = 0; j < 8; j++) acc[i][j] = 0.f;

    const float* qbase = g_qkv + (size_t)b * Tc * 3072 + s * 1024 + h * 64;
    const float* sbase = sb + (size_t)b * Tc * 32;
    const int tstart = slice * (Tc / NSLICE);

    for (int t0 = tstart; t0 < tstart + Tc / NSLICE; t0 += 64) {
#pragma unroll
        for (int i = 0; i < 2; i++) {               // sb 64x32
            int e = tid + i * 256;
            int tt = e >> 3, k4 = (e & 7) * 4;
            *(float4*)&sbs[tt * 36 + k4] =
                *(const float4*)(sbase + (size_t)(t0 + tt) * 32 + k4);
        }
#pragma unroll
        for (int i = 0; i < 4; i++) {               // q 64x64
            int e = tid + i * 256;
            int tt = e >> 4, d4 = (e & 15) * 4;
            *(float4*)&qs[tt * 68 + d4] =
                *(const float4*)(qbase + (size_t)(t0 + tt) * 3072 + d4);
        }
        __syncthreads();
#pragma unroll
        for (int i = 0; i < 16; i++) {
            int t = sub + i * 4;
            float4 sv = *(const float4*)&sbs[t * 36 + k0];
            float4 q0 = *(const float4*)&qs[t * 68 + d0];
            float4 q1 = *(const float4*)&qs[t * 68 + d0 + 4];
            float sk[4] = { sv.x, sv.y, sv.z, sv.w };
            float qv[8] = { q0.x, q0.y, q0.z, q0.w, q1.x, q1.y, q1.z, q1.w };
#pragma unroll
            for (int ki = 0; ki < 4; ki++)
#pragma unroll
                for (int j = 0; j < 8; j++)
                    acc[ki][j] = fmaf(sk[ki], qv[j], acc[ki][j]);
        }
        __syncthreads();
    }

    // reduce the 4 sub-phases via smem (reuses buf)
    float* red = buf;                               // [4][2048]
#pragma unroll
    for (int ki = 0; ki < 4; ki++)
#pragma unroll
        for (int j = 0; j < 8; j++)
            red[sub * 2048 + (k0 + ki) * 64 + d0 + j] = acc[ki][j];
    __syncthreads();

    float* outp = g_specp[slice] + ((size_t)(s * (Bc * Hc) + bh)) * Kc * HDc;
    for (int e = tid; e < 2048; e += 256)
        outp[e] = (red[e] + red[2048 + e]) + (red[4096 + e] + red[6144 + e]);
}

__global__ void spec_reduce_kernel()
{
    int i = (blockIdx.x * blockDim.x + threadIdx.x) * 4;
    float4 a = *(const float4*)&g_specp[0][i];
    float4 b = *(const float4*)&g_specp[1][i];
    float4 c = *(const float4*)&g_specp[2][i];
    float4 d = *(const float4*)&g_specp[3][i];
    *(float4*)&g_spec[i] = make_float4((a.x + b.x) + (c.x + d.x),
                                       (a.y + b.y) + (c.y + d.y),
                                       (a.z + b.z) + (c.z + d.z),
                                       (a.w + b.w) + (c.w + d.w));
}

// ---------------------------------------------------------------------------
// attn_spec + FitzHugh-Nagumo dynamics (constant along HD -> scalar ODE)
// ---------------------------------------------------------------------------
__global__ void soliton_kernel(
    const float* __restrict__ d_a, const float* __restrict__ d_b,
    const float* __restrict__ filt, float* __restrict__ out_resp)
{
    const int idx = blockIdx.x * blockDim.x + threadIdx.x;
    if (idx >= Bc * Hc * Kc) return;
    const int bh = idx >> 5, k = idx & 31;
    const int h = bh & 15;

    const size_t specN = (size_t)Bc * Hc * Kc * HDc;
    const float* qv = g_spec + (size_t)idx * 64;
    const float* kv = g_spec + specN + (size_t)idx * 64;
    float dot = 0.f;
#pragma unroll
    for (int d = 0; d < 64; d++) dot = fmaf(qv[d], kv[d], dot);

    float f = 1.f / (1.f + expf(-filt[h * 32 + k]));
    float stim = dot * 0.125f * f;

    const float a = d_a[0], bb = d_b[0];
    float scale = fmaxf(fabsf(stim), 1e-6f);
    float sn = stim / scale;
    float I = (fabsf(stim) > 0.5f) ? sn : sn * 0.1f;
    float v = 0.f, w = 0.f;
    const float dt = 0.2f;
#pragma unroll
    for (int s = 0; s < 5; s++) {
        float dv = v - v * v * v * (1.f / 3.f) - w + I;
        float dw = (v + a - bb * w) * 10.f;
        v = fminf(fmaxf(v + dt * dv, -3.f), 3.f);
        w = fminf(fmaxf(w + dt * dw, -3.f), 3.f);
    }
    float resp = v * scale;
    out_resp[idx] = resp;

    const float* vv = g_spec + 2 * specN + (size_t)idx * 64;
    float* ws = g_ws + (size_t)idx * 64;
#pragma unroll
    for (int d = 0; d < 64; d++) ws[d] = resp * vv[d];
}

// ---------------------------------------------------------------------------
// Recombine: mid[b,t,h*64+d] = sum_k sb[b,t,k] * ws[b,h,k,d] -> bf16 hi/lo
// ---------------------------------------------------------------------------
__global__ __launch_bounds__(256) void recombine_kernel(const float* __restrict__ sb)
{
    const int bh = blockIdx.x;
    const int b = bh >> 4, h = bh & 15;
    const int t0 = blockIdx.y * 128;
    const int tid = threadIdx.x;

    __shared__ float ws_s[32][65];
    __shared__ float sbs[128][33];

#pragma unroll
    for (int i = 0; i < 2; i++) {
        int e = tid + i * 256;
        int kk = e >> 4, d4 = (e & 15) * 4;
        float4 v = *(const float4*)(g_ws + ((size_t)bh * 32 + kk) * 64 + d4);
        ws_s[kk][d4 + 0] = v.x; ws_s[kk][d4 + 1] = v.y;
        ws_s[kk][d4 + 2] = v.z; ws_s[kk][d4 + 3] = v.w;
    }
    const float* sbase = sb + (size_t)b * Tc * 32;
#pragma unroll
    for (int i = 0; i < 4; i++) {
        int e = tid + i * 256;
        int tt = e >> 3, k4 = (e & 7) * 4;
        float4 v = *(const float4*)(sbase + (size_t)(t0 + tt) * 32 + k4);
        sbs[tt][k4 + 0] = v.x; sbs[tt][k4 + 1] = v.y;
        sbs[tt][k4 + 2] = v.z; sbs[tt][k4 + 3] = v.w;
    }
    __syncthreads();

    for (int e = tid; e < 128 * 64; e += 256) {
        int t = e >> 6, d = e & 63;
        float acc = 0.f;
#pragma unroll
        for (int k = 0; k < 32; k++)
            acc = fmaf(sbs[t][k], ws_s[k][d], acc);
        size_t oi = (size_t)(b * Tc + t0 + t) * Dc + h * 64 + d;
        __nv_bfloat16 hh = __float2bfloat16_rn(acc);
        g_mhi[oi] = hh;
        g_mlo[oi] = __float2bfloat16_rn(acc - __bfloat162float(hh));
    }
}

// ---------------------------------------------------------------------------
// Launch
// ---------------------------------------------------------------------------
extern "C" void kernel_launch(void* const* d_in, const int* in_sizes, int n_in,
                              void* d_out, int out_size)
{
    const float* x    = (const float*)d_in[0];
    const float* sb   = (const float*)d_in[1];
    const float* Wqkv = (const float*)d_in[2];
    const float* Wout = (const float*)d_in[3];
    const float* a    = (const float*)d_in[4];
    const float* b    = (const float*)d_in[5];
    const float* W1   = (const float*)d_in[6];
    const float* b1   = (const float*)d_in[7];
    const float* W2   = (const float*)d_in[8];
    const float* b2   = (const float*)d_in[9];
    const float* filt = (const float*)d_in[10];

    float* out       = (float*)d_out;
    float* out_pulse = out + (size_t)Bc * Tc * Dc;
    float* out_resp  = out_pulse + Bc * Hc;

    float* pqkv = nullptr;
    cudaGetSymbolAddress((void**)&pqkv, g_qkv);
    __nv_bfloat16 *pxhi, *pxlo, *pwqhi, *pwqlo, *pwohi, *pwolo, *pmhi, *pmlo;
    cudaGetSymbolAddress((void**)&pxhi, g_xhi);
    cudaGetSymbolAddress((void**)&pxlo, g_xlo);
    cudaGetSymbolAddress((void**)&pwqhi, g_wqhi);
    cudaGetSymbolAddress((void**)&pwqlo, g_wqlo);
    cudaGetSymbolAddress((void**)&pwohi, g_wohi);
    cudaGetSymbolAddress((void**)&pwolo, g_wolo);
    cudaGetSymbolAddress((void**)&pmhi, g_mhi);
    cudaGetSymbolAddress((void**)&pmlo, g_mlo);

    const int GEMM_SMEM = 2 * STAGE_B;   // 81920 B
    cudaFuncSetAttribute(gemm_mma, cudaFuncAttributeMaxDynamicSharedMemorySize, GEMM_SMEM);

    // 0) bf16 hi/lo splits
    {
        int n4 = (Bc * Tc * Dc) / 4;
        split_bf16<<<(n4 + 255) / 256, 256>>>(x, pxhi, pxlo, n4);
        n4 = (3 * Dc * Dc) / 4;
        split_bf16<<<(n4 + 255) / 256, 256>>>(Wqkv, pwqhi, pwqlo, n4);
        n4 = (Dc * Dc) / 4;
        split_bf16<<<(n4 + 255) / 256, 256>>>(Wout, pwohi, pwolo, n4);
    }

    // 1) QKV projection: (16384 x 1024) @ (3072 x 1024)^T  [mma.sync bf16]
    gemm_mma<<<dim3(3 * Dc / 128, Bc * Tc / 128), 256, GEMM_SMEM>>>(
        pxhi, pxlo, pwqhi, pwqlo, pqkv, Bc * Tc, 3 * Dc);

    // 2) Pulse widths
    qm_pulse_kernel<<<Bc * Hc, 256>>>(W1, b1, W2, b2, out_pulse);

    // 3) Spectral projections q/k/v (partials + reduce)
    spec_part_kernel<<<dim3(Bc * Hc, 3, NSLICE), 256>>>(sb);
    spec_reduce_kernel<<<(3 * Bc * Hc * Kc * HDc) / (256 * 4), 256>>>();

    // 4) soliton dynamics + ws
    soliton_kernel<<<(Bc * Hc * Kc + 255) / 256, 256>>>(a, b, filt, out_resp);

    // 5) Recombine -> mid (bf16 hi/lo)
    recombine_kernel<<<dim3(Bc * Hc, Tc / 128), 256>>>(sb);

    // 6) Output projection: (16384 x 1024) @ (1024 x 1024)^T  [mma.sync bf16]
    gemm_mma<<<dim3(Dc / 128, Bc * Tc / 128), 256, GEMM_SMEM>>>(
        pmhi, pmlo, pwohi, pwolo, out, Bc * Tc, Dc);
}

// round 7
// speedup vs baseline: 7.2837x; 5.1650x over previous
#include <cuda_runtime.h>
#include <math.h>
#include <stdint.h>

// Problem constants
#define Bc  4
#define Tc  4096
#define Dc  1024
#define Hc  16
#define HDc 64
#define Kc  32

#define NS1 64      // t-slices for xs build
#define SKS 16      // split-K for spec GEMM
#define SKZ 32      // split-K for Z GEMM

// ---------------- scratch (static device arrays) ----------------
__device__ float g_xs_p[NS1 * 128 * 1024];      // xs partials  (33.5 MB)
__device__ float g_xm_p[NS1 * Bc * 1024];       // xmean partials
__device__ float g_xs[128 * 1024];              // xs[b*32+k][d] = sum_t sb*x
__device__ float g_xm[Bc * 1024];               // sum_t x
__device__ float g_spec_p[SKS * 128 * 3072];    // spec GEMM partials (25 MB)
__device__ float g_spec3[128 * 3072];           // [m=b*32+k][s*1024+h*64+d]
__device__ float g_ws2[128 * 1024];             // resp * v_spec, flat (m, D)
__device__ float g_Zp[SKZ * 128 * 1024];        // Z GEMM partials (16.8 MB)
__device__ float g_Z[128 * 1024];               // ws2 @ W_out^T

// ---------------------------------------------------------------------------
// K1: xs[b,k,d] = sum_t sb[b,t,k] * x[b,t,d]  (t-sliced partials)
//     xm[b,d]   = sum_t x[b,t,d]
// grid (b=4, slice=64), 256 threads, thread owns 4 d's x (32 k + mean).
// ---------------------------------------------------------------------------
__global__ __launch_bounds__(256) void xs_part_kernel(
    const float* __restrict__ x, const float* __restrict__ sb)
{
    const int b = blockIdx.x, s = blockIdx.y;
    const int tid = threadIdx.x;
    const int d0 = tid * 4;
    const int t0 = s * 64;

    __shared__ float sbs[64][32];
    {   // load sb tile 64x32 (2 float4 per thread)
        int e = tid;
#pragma unroll
        for (int i = 0; i < 2; i++, e += 256) {
            int tt = e >> 3, k4 = (e & 7) * 4;
            *(float4*)&sbs[tt][k4] =
                *(const float4*)(sb + ((size_t)b * Tc + t0 + tt) * 32 + k4);
        }
    }
    __syncthreads();

    float acc[32][4];
#pragma unroll
    for (int k = 0; k < 32; k++)
#pragma unroll
        for (int j = 0; j < 4; j++) acc[k][j] = 0.f;
    float am[4] = {0.f, 0.f, 0.f, 0.f};

    const float* xb = x + ((size_t)b * Tc + t0) * Dc + d0;
    for (int t = 0; t < 64; t++) {
        float4 xv = *(const float4*)(xb + (size_t)t * Dc);
        float v[4] = { xv.x, xv.y, xv.z, xv.w };
#pragma unroll
        for (int j = 0; j < 4; j++) am[j] += v[j];
#pragma unroll
        for (int k = 0; k < 32; k++) {
            float sk = sbs[t][k];
#pragma unroll
            for (int j = 0; j < 4; j++) acc[k][j] = fmaf(sk, v[j], acc[k][j]);
        }
    }

    float* op = g_xs_p + (size_t)s * 131072 + (size_t)b * 32 * 1024 + d0;
#pragma unroll
    for (int k = 0; k < 32; k++)
        *(float4*)(op + k * 1024) = make_float4(acc[k][0], acc[k][1],
                                                acc[k][2], acc[k][3]);
    *(float4*)(g_xm_p + (size_t)s * 4096 + b * 1024 + d0) =
        make_float4(am[0], am[1], am[2], am[3]);
}

// ---------------------------------------------------------------------------
// Generic split reduce: O[i] = sum_s P[s*n4 + i]  (float4 granularity)
// ---------------------------------------------------------------------------
__global__ void reduce_sk(const float* __restrict__ P, float* __restrict__ O,
                          int S, int n4)
{
    int i = blockIdx.x * blockDim.x + threadIdx.x;
    if (i >= n4) return;
    float4 a = make_float4(0.f, 0.f, 0.f, 0.f);
    for (int s = 0; s < S; s++) {
        float4 v = ((const float4*)P)[(size_t)s * n4 + i];
        a.x += v.x; a.y += v.y; a.z += v.z; a.w += v.w;
    }
    ((float4*)O)[i] = a;
}

// ---------------------------------------------------------------------------
// GEMM NT with split-K, M=128 fixed:
// Cp[sk][m][n] = sum_{k in split} A[m][k] * Bm[n][k]
// A: 128x1024 row-major.  Bm: Nx1024 row-major.  128-wide N tiles.
// (proven round-1 structure: 8x8 regs per thread, ~35 TF/s)
// ---------------------------------------------------------------------------
__global__ __launch_bounds__(256) void gemm_nt_sk(
    const float* __restrict__ A, const float* __restrict__ Bm,
    float* __restrict__ Cp, int N, int kPerSplit)
{
    __shared__ float As[8][128];
    __shared__ float Bs[8][128];
    const int tid = threadIdx.x;
    const int col0 = blockIdx.x * 128;
    const int kb = blockIdx.z * kPerSplit;
    const int lrow = tid >> 1, lk = (tid & 1) * 4;
    const int ty = tid >> 4, tx = tid & 15;

    float acc[8][8];
#pragma unroll
    for (int i = 0; i < 8; i++)
#pragma unroll
        for (int j = 0; j < 8; j++) acc[i][j] = 0.f;

    const float* Bp = Bm + (size_t)col0 * 1024;

    for (int k0 = kb; k0 < kb + kPerSplit; k0 += 8) {
        float4 av = *(const float4*)(A  + (size_t)lrow * 1024 + k0 + lk);
        float4 bv = *(const float4*)(Bp + (size_t)lrow * 1024 + k0 + lk);
        As[lk + 0][lrow] = av.x; As[lk + 1][lrow] = av.y;
        As[lk + 2][lrow] = av.z; As[lk + 3][lrow] = av.w;
        Bs[lk + 0][lrow] = bv.x; Bs[lk + 1][lrow] = bv.y;
        Bs[lk + 2][lrow] = bv.z; Bs[lk + 3][lrow] = bv.w;
        __syncthreads();
#pragma unroll
        for (int kk = 0; kk < 8; kk++) {
            float ra[8], rb[8];
#pragma unroll
            for (int i = 0; i < 8; i++) ra[i] = As[kk][ty * 8 + i];
#pragma unroll
            for (int j = 0; j < 8; j++) rb[j] = Bs[kk][tx * 8 + j];
#pragma unroll
            for (int i = 0; i < 8; i++)
#pragma unroll
                for (int j = 0; j < 8; j++)
                    acc[i][j] = fmaf(ra[i], rb[j], acc[i][j]);
        }
        __syncthreads();
    }

    float* C = Cp + (size_t)blockIdx.z * 128 * N;
#pragma unroll
    for (int i = 0; i < 8; i++) {
        float* Cr = C + (size_t)(ty * 8 + i) * N + col0 + tx * 8;
#pragma unroll
        for (int j = 0; j < 8; j += 4)
            *(float4*)(Cr + j) = make_float4(acc[i][j], acc[i][j + 1],
                                             acc[i][j + 2], acc[i][j + 3]);
    }
}

// ---------------------------------------------------------------------------
// qm + pulse-width MLP.  qm[b,h*64+o] = (xm[b,:] . Wqkv[h*64+o,:]) / T
// One block per (b,h). 256 threads: 64 outputs x 4 partial dots.
// ---------------------------------------------------------------------------
__global__ __launch_bounds__(256) void qm_pulse_kernel(
    const float* __restrict__ Wqkv,
    const float* __restrict__ W1, const float* __restrict__ b1,
    const float* __restrict__ W2, const float* __restrict__ b2,
    float* __restrict__ out_pulse)
{
    const int bh = blockIdx.x;
    const int b = bh >> 4, h = bh & 15;
    const int tid = threadIdx.x;
    const int o = tid >> 2, p = tid & 3;

    const float* xm = g_xm + b * 1024 + p * 256;
    const float* wr = Wqkv + (size_t)(h * 64 + o) * 1024 + p * 256;
    float s = 0.f;
#pragma unroll 8
    for (int i = 0; i < 256; i++) s = fmaf(xm[i], wr[i], s);

    __shared__ float red[64][4];
    __shared__ float qm[64];
    red[o][p] = s;
    __syncthreads();
    if (tid < 64)
        qm[tid] = (red[tid][0] + red[tid][1] + red[tid][2] + red[tid][3])
                  * (1.0f / Tc);
    __syncthreads();
    if (tid < 32) {
        float acc = b1[tid];
#pragma unroll
        for (int dd = 0; dd < 64; dd++)
            acc = fmaf(qm[dd], W1[tid * 64 + dd], acc);
        float h1 = acc / (1.f + expf(-acc));        // silu
        float pp = h1 * W2[tid];
#pragma unroll
        for (int off = 16; off; off >>= 1)
            pp += __shfl_down_sync(0xffffffffu, pp, off);
        if (tid == 0) {
            float xv = pp + b2[0];
            float sp = (xv > 20.f) ? xv : log1pf(expf(xv));  // softplus
            out_pulse[bh] = 4.0f + sp;
        }
    }
}

// ---------------------------------------------------------------------------
// Soliton: per (m=b*32+k, h): attn dot, FHN scalar ODE, response, ws2.
// ---------------------------------------------------------------------------
__global__ void soliton_kernel(
    const float* __restrict__ d_a, const float* __restrict__ d_b,
    const float* __restrict__ filt, float* __restrict__ out_resp)
{
    const int gid = blockIdx.x * blockDim.x + threadIdx.x;   // 0..2047
    if (gid >= 2048) return;
    const int m = gid >> 4, h = gid & 15;
    const int b = m >> 5, k = m & 31;

    const float* row = g_spec3 + (size_t)m * 3072 + h * 64;
    float dot = 0.f;
#pragma unroll
    for (int d = 0; d < 64; d++) dot = fmaf(row[d], row[1024 + d], dot);

    float f = 1.f / (1.f + expf(-filt[h * 32 + k]));
    float stim = dot * 0.125f * f;                 // /sqrt(64) * sigmoid

    const float a = d_a[0], bb = d_b[0];
    float scale = fmaxf(fabsf(stim), 1e-6f);
    float sn = stim / scale;
    float I = (fabsf(stim) > 0.5f) ? sn : sn * 0.1f;
    float v = 0.f, w = 0.f;
    const float dt = 0.2f;
#pragma unroll
    for (int s = 0; s < 5; s++) {
        float dv = v - v * v * v * (1.f / 3.f) - w + I;
        float dw = (v + a - bb * w) * 10.f;
        v = fminf(fmaxf(v + dt * dv, -3.f), 3.f);
        w = fminf(fmaxf(w + dt * dw, -3.f), 3.f);
    }
    float resp = v * scale;
    out_resp[b * 512 + h * 32 + k] = resp;

    float* wsr = g_ws2 + (size_t)m * 1024 + h * 64;
#pragma unroll
    for (int d = 0; d < 64; d++) wsr[d] = resp * row[2048 + d];
}

// ---------------------------------------------------------------------------
// K_out: out[b,t,:] = sum_k sb[b,t,k] * Z[b*32+k][:]
// grid (b=4, ttile=64 of 64 t's); thread owns 4 d's, Z column in regs.
// ---------------------------------------------------------------------------
__global__ __launch_bounds__(256) void out_expand_kernel(
    const float* __restrict__ sb, float* __restrict__ out)
{
    const int b = blockIdx.x, tt0 = blockIdx.y * 64;
    const int tid = threadIdx.x;
    const int d0 = tid * 4;

    __shared__ float sbs[64][32];
    {
        int e = tid;
#pragma unroll
        for (int i = 0; i < 2; i++, e += 256) {
            int ttt = e >> 3, k4 = (e & 7) * 4;
            *(float4*)&sbs[ttt][k4] =
                *(const float4*)(sb + ((size_t)b * Tc + tt0 + ttt) * 32 + k4);
        }
    }

    float zr[32][4];
#pragma unroll
    for (int k = 0; k < 32; k++) {
        float4 z = *(const float4*)(g_Z + (size_t)(b * 32 + k) * 1024 + d0);
        zr[k][0] = z.x; zr[k][1] = z.y; zr[k][2] = z.z; zr[k][3] = z.w;
    }
    __syncthreads();

    float* ob = out + ((size_t)b * Tc + tt0) * Dc + d0;
    for (int t = 0; t < 64; t++) {
        float a0 = 0.f, a1 = 0.f, a2 = 0.f, a3 = 0.f;
#pragma unroll
        for (int k = 0; k < 32; k++) {
            float s = sbs[t][k];
            a0 = fmaf(s, zr[k][0], a0);
            a1 = fmaf(s, zr[k][1], a1);
            a2 = fmaf(s, zr[k][2], a2);
            a3 = fmaf(s, zr[k][3], a3);
        }
        *(float4*)(ob + (size_t)t * Dc) = make_float4(a0, a1, a2, a3);
    }
}

// ---------------------------------------------------------------------------
// Launch
// Inputs: x, spectral_basis, W_qkv, W_out, a, b, W1, b1, W2, b2, spectral_filter
// Outputs: out (B*T*D) ++ pulse_widths (B*H) ++ response (B*H*K)
// ---------------------------------------------------------------------------
extern "C" void kernel_launch(void* const* d_in, const int* in_sizes, int n_in,
                              void* d_out, int out_size)
{
    const float* x    = (const float*)d_in[0];
    const float* sb   = (const float*)d_in[1];
    const float* Wqkv = (const float*)d_in[2];
    const float* Wout = (const float*)d_in[3];
    const float* a    = (const float*)d_in[4];
    const float* b    = (const float*)d_in[5];
    const float* W1   = (const float*)d_in[6];
    const float* b1   = (const float*)d_in[7];
    const float* W2   = (const float*)d_in[8];
    const float* b2   = (const float*)d_in[9];
    const float* filt = (const float*)d_in[10];

    float* out       = (float*)d_out;
    float* out_pulse = out + (size_t)Bc * Tc * Dc;
    float* out_resp  = out_pulse + Bc * Hc;

    float *pxs_p, *pxm_p, *pxs, *pxm, *pspec_p, *pspec3, *pws2, *pZp, *pZ;
    cudaGetSymbolAddress((void**)&pxs_p, g_xs_p);
    cudaGetSymbolAddress((void**)&pxm_p, g_xm_p);
    cudaGetSymbolAddress((void**)&pxs, g_xs);
    cudaGetSymbolAddress((void**)&pxm, g_xm);
    cudaGetSymbolAddress((void**)&pspec_p, g_spec_p);
    cudaGetSymbolAddress((void**)&pspec3, g_spec3);
    cudaGetSymbolAddress((void**)&pws2, g_ws2);
    cudaGetSymbolAddress((void**)&pZp, g_Zp);
    cudaGetSymbolAddress((void**)&pZ, g_Z);

    // 1) xs = sb^T x (per batch) + xmean, t-sliced partials then reduce
    xs_part_kernel<<<dim3(Bc, NS1), 256>>>(x, sb);
    reduce_sk<<<(32768 + 255) / 256, 256>>>(pxs_p, pxs, NS1, 32768);
    reduce_sk<<<(1024 + 255) / 256, 256>>>(pxm_p, pxm, NS1, 1024);

    // 2) pulse widths (from xmean)
    qm_pulse_kernel<<<Bc * Hc, 256>>>(Wqkv, W1, b1, W2, b2, out_pulse);

    // 3) spec3 = xs @ Wqkv^T   (128 x 3072, split-K 16)
    gemm_nt_sk<<<dim3(24, 1, SKS), 256>>>(pxs, Wqkv, pspec_p, 3072, 1024 / SKS);
    reduce_sk<<<(98304 + 255) / 256, 256>>>(pspec_p, pspec3, SKS, 98304);

    // 4) soliton dynamics -> response + ws2
    soliton_kernel<<<8, 256>>>(a, b, filt, out_resp);

    // 5) Z = ws2 @ Wout^T   (128 x 1024, split-K 32)
    gemm_nt_sk<<<dim3(8, 1, SKZ), 256>>>(pws2, Wout, pZp, 1024, 1024 / SKZ);
    reduce_sk<<<(32768 + 255) / 256, 256>>>(pZp, pZ, SKZ, 32768);

    // 6) out = sb @ Z (per batch)
    out_expand_kernel<<<dim3(Bc, Tc / 64), 256>>>(sb, out);
}

// round 8
// speedup vs baseline: 8.7389x; 1.1998x over previous
#include <cuda_runtime.h>
#include <math.h>
#include <stdint.h>

// Problem constants
#define Bc  4
#define Tc  4096
#define Dc  1024
#define Hc  16
#define HDc 64
#define Kc  32

#define NS1 64      // t-slices for xs build
#define SKS 16      // split-K for spec GEMM
#define SKZ 32      // split-K for Z GEMM

// ---------------- scratch (static device arrays) ----------------
__device__ float g_xs_p[NS1 * 128 * 1024];      // xs partials
__device__ float g_xm_p[NS1 * Bc * 1024];       // xmean partials
__device__ float g_xs[128 * 1024];              // xs[b*32+k][d]
__device__ float g_xm[Bc * 1024];               // sum_t x
__device__ float g_qm[Bc * 1024];               // xm @ Wq^T (unnormalized)
__device__ float g_spec_p[SKS * 128 * 3072];    // spec GEMM partials
__device__ float g_spec3[128 * 3072];           // [m][s*1024+h*64+d]
__device__ float g_ws2[128 * 1024];             // resp * v_spec
__device__ float g_Zp[SKZ * 128 * 1024];        // Z GEMM partials
__device__ float g_Z[128 * 1024];               // ws2 @ W_out^T

// ---------------------------------------------------------------------------
// K1: xs[b,k,d] = sum_t sb[b,t,k] * x[b,t,d]  (t-sliced partials)
//     xm[b,d]   = sum_t x[b,t,d]
// grid (b=4, slice=64), 256 threads, thread owns 4 d's x 32 k.
// ---------------------------------------------------------------------------
__global__ __launch_bounds__(256) void xs_part_kernel(
    const float* __restrict__ x, const float* __restrict__ sb)
{
    const int b = blockIdx.x, s = blockIdx.y;
    const int tid = threadIdx.x;
    const int d0 = tid * 4;
    const int t0 = s * 64;

    __shared__ __align__(16) float sbs[64][32];
    {
        int e = tid;
#pragma unroll
        for (int i = 0; i < 2; i++, e += 256) {
            int tt = e >> 3, k4 = (e & 7) * 4;
            *(float4*)&sbs[tt][k4] =
                *(const float4*)(sb + ((size_t)b * Tc + t0 + tt) * 32 + k4);
        }
    }
    __syncthreads();

    float acc[32][4];
#pragma unroll
    for (int k = 0; k < 32; k++)
#pragma unroll
        for (int j = 0; j < 4; j++) acc[k][j] = 0.f;
    float am[4] = {0.f, 0.f, 0.f, 0.f};

    const float* xb = x + ((size_t)b * Tc + t0) * Dc + d0;
    for (int t = 0; t < 64; t++) {
        float4 xv = *(const float4*)(xb + (size_t)t * Dc);
        float v[4] = { xv.x, xv.y, xv.z, xv.w };
#pragma unroll
        for (int j = 0; j < 4; j++) am[j] += v[j];
#pragma unroll
        for (int k8 = 0; k8 < 8; k8++) {              // float4 sbs reads
            float4 sv = *(const float4*)&sbs[t][k8 * 4];
            float sk[4] = { sv.x, sv.y, sv.z, sv.w };
#pragma unroll
            for (int ki = 0; ki < 4; ki++)
#pragma unroll
                for (int j = 0; j < 4; j++)
                    acc[k8 * 4 + ki][j] = fmaf(sk[ki], v[j], acc[k8 * 4 + ki][j]);
        }
    }

    float* op = g_xs_p + (size_t)s * 131072 + (size_t)b * 32 * 1024 + d0;
#pragma unroll
    for (int k = 0; k < 32; k++)
        *(float4*)(op + k * 1024) = make_float4(acc[k][0], acc[k][1],
                                                acc[k][2], acc[k][3]);
    *(float4*)(g_xm_p + (size_t)s * 4096 + b * 1024 + d0) =
        make_float4(am[0], am[1], am[2], am[3]);
}

// ---------------------------------------------------------------------------
// Combined reduce of xs (32768 f4) and xm (1024 f4) partials over NS1 slices.
// ---------------------------------------------------------------------------
__global__ void reduce_xs_xm()
{
    int i = blockIdx.x * blockDim.x + threadIdx.x;
    if (i < 32768) {
        float4 a = make_float4(0.f, 0.f, 0.f, 0.f);
#pragma unroll 4
        for (int s = 0; s < NS1; s++) {
            float4 v = ((const float4*)g_xs_p)[(size_t)s * 32768 + i];
            a.x += v.x; a.y += v.y; a.z += v.z; a.w += v.w;
        }
        ((float4*)g_xs)[i] = a;
    } else if (i < 32768 + 1024) {
        int j = i - 32768;
        float4 a = make_float4(0.f, 0.f, 0.f, 0.f);
#pragma unroll 4
        for (int s = 0; s < NS1; s++) {
            float4 v = ((const float4*)g_xm_p)[(size_t)s * 1024 + j];
            a.x += v.x; a.y += v.y; a.z += v.z; a.w += v.w;
        }
        ((float4*)g_xm)[j] = a;
    }
}

// ---------------------------------------------------------------------------
// Generic split reduce: O[i] = sum_s P[s*n4 + i]  (float4 granularity)
// ---------------------------------------------------------------------------
__global__ void reduce_sk(const float* __restrict__ P, float* __restrict__ O,
                          int S, int n4)
{
    int i = blockIdx.x * blockDim.x + threadIdx.x;
    if (i >= n4) return;
    float4 a = make_float4(0.f, 0.f, 0.f, 0.f);
    for (int s = 0; s < S; s++) {
        float4 v = ((const float4*)P)[(size_t)s * n4 + i];
        a.x += v.x; a.y += v.y; a.z += v.z; a.w += v.w;
    }
    ((float4*)O)[i] = a;
}

// ---------------------------------------------------------------------------
// GEMM NT with split-K, M=128 fixed (8x8 regs/thread, 128x128 tiles)
// ---------------------------------------------------------------------------
__global__ __launch_bounds__(256) void gemm_nt_sk(
    const float* __restrict__ A, const float* __restrict__ Bm,
    float* __restrict__ Cp, int N, int kPerSplit)
{
    __shared__ float As[8][128];
    __shared__ float Bs[8][128];
    const int tid = threadIdx.x;
    const int col0 = blockIdx.x * 128;
    const int kb = blockIdx.z * kPerSplit;
    const int lrow = tid >> 1, lk = (tid & 1) * 4;
    const int ty = tid >> 4, tx = tid & 15;

    float acc[8][8];
#pragma unroll
    for (int i = 0; i < 8; i++)
#pragma unroll
        for (int j = 0; j < 8; j++) acc[i][j] = 0.f;

    const float* Bp = Bm + (size_t)col0 * 1024;

    for (int k0 = kb; k0 < kb + kPerSplit; k0 += 8) {
        float4 av = *(const float4*)(A  + (size_t)lrow * 1024 + k0 + lk);
        float4 bv = *(const float4*)(Bp + (size_t)lrow * 1024 + k0 + lk);
        As[lk + 0][lrow] = av.x; As[lk + 1][lrow] = av.y;
        As[lk + 2][lrow] = av.z; As[lk + 3][lrow] = av.w;
        Bs[lk + 0][lrow] = bv.x; Bs[lk + 1][lrow] = bv.y;
        Bs[lk + 2][lrow] = bv.z; Bs[lk + 3][lrow] = bv.w;
        __syncthreads();
#pragma unroll
        for (int kk = 0; kk < 8; kk++) {
            float ra[8], rb[8];
#pragma unroll
            for (int i = 0; i < 8; i++) ra[i] = As[kk][ty * 8 + i];
#pragma unroll
            for (int j = 0; j < 8; j++) rb[j] = Bs[kk][tx * 8 + j];
#pragma unroll
            for (int i = 0; i < 8; i++)
#pragma unroll
                for (int j = 0; j < 8; j++)
                    acc[i][j] = fmaf(ra[i], rb[j], acc[i][j]);
        }
        __syncthreads();
    }

    float* C = Cp + (size_t)blockIdx.z * 128 * N;
#pragma unroll
    for (int i = 0; i < 8; i++) {
        float* Cr = C + (size_t)(ty * 8 + i) * N + col0 + tx * 8;
#pragma unroll
        for (int j = 0; j < 8; j += 4)
            *(float4*)(Cr + j) = make_float4(acc[i][j], acc[i][j + 1],
                                             acc[i][j + 2], acc[i][j + 3]);
    }
}

// ---------------------------------------------------------------------------
// qm GEMV: g_qm[b*1024+o] = xm[b,:] . Wqkv[o,:]   (o < 1024 = q rows)
// One warp per (b,o): 512 blocks x 8 warps = 4096 warps. float4 coalesced.
// ---------------------------------------------------------------------------
__global__ __launch_bounds__(256) void qm_gemv_kernel(
    const float* __restrict__ Wqkv)
{
    const int w = blockIdx.x * 8 + (threadIdx.x >> 5);   // 0..4095
    const int lane = threadIdx.x & 31;
    const int b = w >> 10, o = w & 1023;

    const float4* xm = (const float4*)(g_xm + b * 1024);
    const float4* wr = (const float4*)(Wqkv + (size_t)o * 1024);
    float s = 0.f;
#pragma unroll
    for (int j = 0; j < 8; j++) {
        float4 a = xm[lane + j * 32];
        float4 c = wr[lane + j * 32];
        s = fmaf(a.x, c.x, s); s = fmaf(a.y, c.y, s);
        s = fmaf(a.z, c.z, s); s = fmaf(a.w, c.w, s);
    }
#pragma unroll
    for (int off = 16; off; off >>= 1)
        s += __shfl_down_sync(0xffffffffu, s, off);
    if (lane == 0) g_qm[b * 1024 + o] = s;
}

// ---------------------------------------------------------------------------
// Fused: blocks 0..7 soliton (FHN scalar ODE -> response + ws2),
//        blocks 8..71 pulse-width MLP per (b,h).
// ---------------------------------------------------------------------------
__global__ __launch_bounds__(256) void soliton_pulse_kernel(
    const float* __restrict__ d_a, const float* __restrict__ d_b,
    const float* __restrict__ filt,
    const float* __restrict__ W1, const float* __restrict__ b1,
    const float* __restrict__ W2, const float* __restrict__ b2,
    float* __restrict__ out_resp, float* __restrict__ out_pulse)
{
    if (blockIdx.x < 8) {
        const int gid = blockIdx.x * 256 + threadIdx.x;   // 0..2047
        const int m = gid >> 4, h = gid & 15;
        const int b = m >> 5, k = m & 31;

        const float* row = g_spec3 + (size_t)m * 3072 + h * 64;
        float dot = 0.f;
#pragma unroll
        for (int d = 0; d < 64; d++) dot = fmaf(row[d], row[1024 + d], dot);

        float f = 1.f / (1.f + expf(-filt[h * 32 + k]));
        float stim = dot * 0.125f * f;

        const float a = d_a[0], bb = d_b[0];
        float scale = fmaxf(fabsf(stim), 1e-6f);
        float sn = stim / scale;
        float I = (fabsf(stim) > 0.5f) ? sn : sn * 0.1f;
        float v = 0.f, w = 0.f;
        const float dt = 0.2f;
#pragma unroll
        for (int s = 0; s < 5; s++) {
            float dv = v - v * v * v * (1.f / 3.f) - w + I;
            float dw = (v + a - bb * w) * 10.f;
            v = fminf(fmaxf(v + dt * dv, -3.f), 3.f);
            w = fminf(fmaxf(w + dt * dw, -3.f), 3.f);
        }
        float resp = v * scale;
        out_resp[b * 512 + h * 32 + k] = resp;

        float* wsr = g_ws2 + (size_t)m * 1024 + h * 64;
#pragma unroll
        for (int d = 0; d < 64; d++) wsr[d] = resp * row[2048 + d];
    } else {
        const int bh = blockIdx.x - 8;                    // 0..63
        const int b = bh >> 4, h = bh & 15;
        const int tid = threadIdx.x;
        if (tid >= 32) return;
        const float* qm = g_qm + b * 1024 + h * 64;
        float acc = b1[tid];
#pragma unroll
        for (int dd = 0; dd < 64; dd++)
            acc = fmaf(qm[dd] * (1.0f / Tc), W1[tid * 64 + dd], acc);
        float h1 = acc / (1.f + expf(-acc));              // silu
        float pp = h1 * W2[tid];
#pragma unroll
        for (int off = 16; off; off >>= 1)
            pp += __shfl_down_sync(0xffffffffu, pp, off);
        if (tid == 0) {
            float xv = pp + b2[0];
            float sp = (xv > 20.f) ? xv : log1pf(expf(xv));  // softplus
            out_pulse[bh] = 4.0f + sp;
        }
    }
}

// ---------------------------------------------------------------------------
// K_out: out[b,t,:] = sum_k sb[b,t,k] * Z[b*32+k][:]
// ---------------------------------------------------------------------------
__global__ __launch_bounds__(256) void out_expand_kernel(
    const float* __restrict__ sb, float* __restrict__ out)
{
    const int b = blockIdx.x, tt0 = blockIdx.y * 64;
    const int tid = threadIdx.x;
    const int d0 = tid * 4;

    __shared__ __align__(16) float sbs[64][32];
    {
        int e = tid;
#pragma unroll
        for (int i = 0; i < 2; i++, e += 256) {
            int ttt = e >> 3, k4 = (e & 7) * 4;
            *(float4*)&sbs[ttt][k4] =
                *(const float4*)(sb + ((size_t)b * Tc + tt0 + ttt) * 32 + k4);
        }
    }

    float zr[32][4];
#pragma unroll
    for (int k = 0; k < 32; k++) {
        float4 z = *(const float4*)(g_Z + (size_t)(b * 32 + k) * 1024 + d0);
        zr[k][0] = z.x; zr[k][1] = z.y; zr[k][2] = z.z; zr[k][3] = z.w;
    }
    __syncthreads();

    float* ob = out + ((size_t)b * Tc + tt0) * Dc + d0;
    for (int t = 0; t < 64; t++) {
        float a0 = 0.f, a1 = 0.f, a2 = 0.f, a3 = 0.f;
#pragma unroll
        for (int k8 = 0; k8 < 8; k8++) {
            float4 sv = *(const float4*)&sbs[t][k8 * 4];
            float sk[4] = { sv.x, sv.y, sv.z, sv.w };
#pragma unroll
            for (int ki = 0; ki < 4; ki++) {
                a0 = fmaf(sk[ki], zr[k8 * 4 + ki][0], a0);
                a1 = fmaf(sk[ki], zr[k8 * 4 + ki][1], a1);
                a2 = fmaf(sk[ki], zr[k8 * 4 + ki][2], a2);
                a3 = fmaf(sk[ki], zr[k8 * 4 + ki][3], a3);
            }
        }
        *(float4*)(ob + (size_t)t * Dc) = make_float4(a0, a1, a2, a3);
    }
}

// ---------------------------------------------------------------------------
// Launch
// Inputs: x, spectral_basis, W_qkv, W_out, a, b, W1, b1, W2, b2, spectral_filter
// Outputs: out (B*T*D) ++ pulse_widths (B*H) ++ response (B*H*K)
// ---------------------------------------------------------------------------
extern "C" void kernel_launch(void* const* d_in, const int* in_sizes, int n_in,
                              void* d_out, int out_size)
{
    const float* x    = (const float*)d_in[0];
    const float* sb   = (const float*)d_in[1];
    const float* Wqkv = (const float*)d_in[2];
    const float* Wout = (const float*)d_in[3];
    const float* a    = (const float*)d_in[4];
    const float* b    = (const float*)d_in[5];
    const float* W1   = (const float*)d_in[6];
    const float* b1   = (const float*)d_in[7];
    const float* W2   = (const float*)d_in[8];
    const float* b2   = (const float*)d_in[9];
    const float* filt = (const float*)d_in[10];

    float* out       = (float*)d_out;
    float* out_pulse = out + (size_t)Bc * Tc * Dc;
    float* out_resp  = out_pulse + Bc * Hc;

    float *pxs, *pspec_p, *pspec3, *pws2, *pZp, *pZ;
    cudaGetSymbolAddress((void**)&pxs, g_xs);
    cudaGetSymbolAddress((void**)&pspec_p, g_spec_p);
    cudaGetSymbolAddress((void**)&pspec3, g_spec3);
    cudaGetSymbolAddress((void**)&pws2, g_ws2);
    cudaGetSymbolAddress((void**)&pZp, g_Zp);
    cudaGetSymbolAddress((void**)&pZ, g_Z);

    // 1) xs = sb^T x (per batch) + xmean; partials then fused reduce
    xs_part_kernel<<<dim3(Bc, NS1), 256>>>(x, sb);
    reduce_xs_xm<<<(32768 + 1024 + 255) / 256, 256>>>();

    // 2) qm GEMV (warp per output)
    qm_gemv_kernel<<<512, 256>>>(Wqkv);

    // 3) spec3 = xs @ Wqkv^T   (128 x 3072, split-K 16)
    gemm_nt_sk<<<dim3(24, 1, SKS), 256>>>(pxs, Wqkv, pspec_p, 3072, 1024 / SKS);
    reduce_sk<<<(98304 + 255) / 256, 256>>>(pspec_p, pspec3, SKS, 98304);

    // 4) soliton dynamics + pulse MLP (fused)
    soliton_pulse_kernel<<<8 + 64, 256>>>(a, b, filt, W1, b1, W2, b2,
                                          out_resp, out_pulse);

    // 5) Z = ws2 @ Wout^T   (128 x 1024, split-K 32)
    gemm_nt_sk<<<dim3(8, 1, SKZ), 256>>>(pws2, Wout, pZp, 1024, 1024 / SKZ);
    reduce_sk<<<(32768 + 255) / 256, 256>>>(pZp, pZ, SKZ, 32768);

    // 6) out = sb @ Z (per batch)
    out_expand_kernel<<<dim3(Bc, Tc / 64), 256>>>(sb, out);
}